// round 5
// baseline (speedup 1.0000x reference)
#include <cuda_runtime.h>
#include <cuda_bf16.h>
#include <mma.h>
#include <math.h>
#include <stdint.h>

using namespace nvcuda;

#define MAXN 4096
#define D    128

// ---------------- scratch (device globals; no allocation allowed) -------------
__device__ float         g_S[(size_t)MAXN * MAXN]; // exp(sim/tau), masked = 0
__device__ __nv_bfloat16 g_hi[MAXN * D];           // hnn hi split
__device__ __nv_bfloat16 g_lo[MAXN * D];           // hnn lo split
__device__ float         g_pos[MAXN];              // exp(cos(hp_x, hp_qx)/tau)
__device__ float         g_loss[MAXN];
__device__ int           g_q[MAXN];                // positive-pair partner

// ---------------- K0: build partner map ---------------------------------------
__global__ void build_q_kernel(const int* __restrict__ pp, int npairs) {
    int r = blockIdx.x * blockDim.x + threadIdx.x;
    if (r < npairs) g_q[pp[2 * r]] = pp[2 * r + 1];
}

// ---------------- K1: normalized hard_neg rows (bf16 hi/lo split) + pos --------
__global__ void prep_kernel(const float* __restrict__ emb, int N) {
    int x = blockIdx.x;
    int d = threadIdx.x;
    int qx = g_q[x];
    int fx = N - 1;
    while (fx == x || fx == qx) fx--;   // largest index not in {x, q[x]}

    float a  = emb[(size_t)x  * D + d];
    float b  = emb[(size_t)qx * D + d];
    float pf = emb[(size_t)fx * D + d];
    float h  = 0.5f * (a + pf);

    float v0 = h * h, v1 = a * a, v2 = b * b, v3 = a * b;
    __shared__ float sh[4][4];
    int lane = d & 31, w = d >> 5;
    #pragma unroll
    for (int o = 16; o; o >>= 1) {
        v0 += __shfl_xor_sync(0xffffffffu, v0, o);
        v1 += __shfl_xor_sync(0xffffffffu, v1, o);
        v2 += __shfl_xor_sync(0xffffffffu, v2, o);
        v3 += __shfl_xor_sync(0xffffffffu, v3, o);
    }
    if (lane == 0) { sh[0][w] = v0; sh[1][w] = v1; sh[2][w] = v2; sh[3][w] = v3; }
    __syncthreads();
    float nn = sh[0][0] + sh[0][1] + sh[0][2] + sh[0][3];
    float inv = 1.0f / fmaxf(sqrtf(nn), 1e-8f);
    float hn = h * inv;
    __nv_bfloat16 hh = __float2bfloat16(hn);
    __nv_bfloat16 hl = __float2bfloat16(hn - __bfloat162float(hh));
    g_hi[(size_t)x * D + d] = hh;
    g_lo[(size_t)x * D + d] = hl;

    if (d == 0) {
        float aa = sh[1][0] + sh[1][1] + sh[1][2] + sh[1][3];
        float bb = sh[2][0] + sh[2][1] + sh[2][2] + sh[2][3];
        float ab = sh[3][0] + sh[3][1] + sh[3][2] + sh[3][3];
        float dot = 2.5f * ab - 0.75f * (aa + bb);
        float nxx = 2.25f * aa + 0.25f * bb - 1.5f * ab;
        float nyy = 2.25f * bb + 0.25f * aa - 1.5f * ab;
        float nx = fmaxf(sqrtf(nxx), 1e-8f);
        float ny = fmaxf(sqrtf(nyy), 1e-8f);
        g_pos[x] = expf((dot / (nx * ny)) * 5.0f);
    }
}

// ---------------- K2: WMMA split-bf16 symmetric GEMM + exp + mask --------------
// 128x128 tile per CTA, upper triangle only, mirror store. 256 threads, 8 warps.
// acc = Ah*Bh + Ah*Bl + Al*Bh in fp32 (effective ~fp32 precision of inputs).
// K in 2 chunks of 64, smem rows padded to 72 bf16 (conflict-free ldmatrix).
#define KP  72
#define TSZ (128 * KP)       // bf16 elements per tile
#define LDS 132              // staging row stride (floats)

__global__ void __launch_bounds__(256) gemm_wmma_kernel(int N) {
    extern __shared__ char smem[];
    __nv_bfloat16* Ah = (__nv_bfloat16*)smem;
    __nv_bfloat16* Al = Ah + TSZ;
    __nv_bfloat16* Bh = Al + TSZ;
    __nv_bfloat16* Bl = Bh + TSZ;
    float* Tst = (float*)smem;          // epilogue staging 128 x LDS (reuses tiles)

    int nb = N >> 7;
    int bid = blockIdx.x;
    int bi = 0, rem = bid;
    while (rem >= nb - bi) { rem -= nb - bi; bi++; }
    int bj = bi + rem;                  // bj >= bi

    int tid = threadIdx.x, wid = tid >> 5;
    int wm = wid >> 1, wn = wid & 1;    // warp tile: rows wm*32..+32, cols wn*64..+64

    wmma::fragment<wmma::accumulator, 16, 16, 16, float> acc[2][4];
    #pragma unroll
    for (int i = 0; i < 2; ++i)
        #pragma unroll
        for (int j = 0; j < 4; ++j) wmma::fill_fragment(acc[i][j], 0.0f);

    #pragma unroll
    for (int ch = 0; ch < 2; ++ch) {
        // load 4 tiles: 128 rows x 64 cols each (bf16), padded rows
        const __nv_bfloat16* srcs[4] = {
            g_hi + (size_t)bi * 128 * D + ch * 64,
            g_lo + (size_t)bi * 128 * D + ch * 64,
            g_hi + (size_t)bj * 128 * D + ch * 64,
            g_lo + (size_t)bj * 128 * D + ch * 64 };
        __nv_bfloat16* dsts[4] = {Ah, Al, Bh, Bl};
        #pragma unroll
        for (int t2 = 0; t2 < 4; ++t2) {
            #pragma unroll
            for (int i = tid; i < 1024; i += 256) {   // 1024 uint4 per tile
                int row = i >> 3, c8 = i & 7;
                *(uint4*)(dsts[t2] + row * KP + c8 * 8) =
                    *(const uint4*)(srcs[t2] + (size_t)row * D + c8 * 8);
            }
        }
        __syncthreads();

        #pragma unroll
        for (int ks = 0; ks < 4; ++ks) {
            wmma::fragment<wmma::matrix_a, 16, 16, 16, __nv_bfloat16, wmma::row_major> a_h[2], a_l[2];
            wmma::fragment<wmma::matrix_b, 16, 16, 16, __nv_bfloat16, wmma::col_major> b_h[4], b_l[4];
            #pragma unroll
            for (int i = 0; i < 2; ++i) {
                const __nv_bfloat16* p = Ah + (wm * 32 + i * 16) * KP + ks * 16;
                wmma::load_matrix_sync(a_h[i], p, KP);
                wmma::load_matrix_sync(a_l[i], p + TSZ, KP);   // Al at fixed offset
            }
            #pragma unroll
            for (int j = 0; j < 4; ++j) {
                const __nv_bfloat16* p = Bh + (wn * 64 + j * 16) * KP + ks * 16;
                wmma::load_matrix_sync(b_h[j], p, KP);
                wmma::load_matrix_sync(b_l[j], p + TSZ, KP);   // Bl at fixed offset
            }
            #pragma unroll
            for (int i = 0; i < 2; ++i)
                #pragma unroll
                for (int j = 0; j < 4; ++j) {
                    wmma::mma_sync(acc[i][j], a_h[i], b_h[j], acc[i][j]);
                    wmma::mma_sync(acc[i][j], a_h[i], b_l[j], acc[i][j]);
                    wmma::mma_sync(acc[i][j], a_l[i], b_h[j], acc[i][j]);
                }
        }
        __syncthreads();
    }

    // stage accumulators to smem
    #pragma unroll
    for (int i = 0; i < 2; ++i)
        #pragma unroll
        for (int j = 0; j < 4; ++j)
            wmma::store_matrix_sync(Tst + (wm * 32 + i * 16) * LDS + wn * 64 + j * 16,
                                    acc[i][j], LDS, wmma::mem_row_major);
    __syncthreads();

    // mask + exp in place
    int m0 = bi * 128, n0 = bj * 128;
    for (int idx = tid; idx < 16384; idx += 256) {
        int r = idx >> 7, c = idx & 127;
        int m = m0 + r, n = n0 + c;
        float a = Tst[r * LDS + c];
        Tst[r * LDS + c] = (n == m || n == g_q[m]) ? 0.0f : __expf(a * 5.0f);
    }
    __syncthreads();

    // direct store: rows m0+r, coalesced cols
    int t = tid & 127, hseg = tid >> 7;
    #pragma unroll 4
    for (int j = 0; j < 64; ++j) {
        int r = j * 2 + hseg;
        g_S[(size_t)(m0 + r) * N + n0 + t] = Tst[r * LDS + t];
    }
    // mirror store: rows n0+c, coalesced cols at m0 (transposed smem read)
    #pragma unroll 4
    for (int j = 0; j < 64; ++j) {
        int c = j * 2 + hseg;
        g_S[(size_t)(n0 + c) * N + m0 + t] = Tst[t * LDS + c];
    }
}

// ---------------- K3 helper: locate bin containing rank k ----------------------
__device__ __forceinline__ void locate_bin(unsigned* hist, int nbins, unsigned k,
                                           unsigned* s_warp, int* s_bin, int* s_krem) {
    int tid = threadIdx.x;
    int per = nbins >> 8;
    unsigned local = 0;
    for (int b = 0; b < per; b++) local += hist[tid * per + b];
    unsigned inc = local;
    int lane = tid & 31, w = tid >> 5;
    #pragma unroll
    for (int o = 1; o < 32; o <<= 1) {
        unsigned t = __shfl_up_sync(0xffffffffu, inc, o);
        if (lane >= o) inc += t;
    }
    if (lane == 31) s_warp[w] = inc;
    __syncthreads();
    unsigned woff = 0;
    for (int ww = 0; ww < w; ++ww) woff += s_warp[ww];
    unsigned excl = woff + inc - local;
    if (excl <= k && k < excl + local) {
        unsigned c = excl;
        for (int b = 0; b < per; b++) {
            unsigned h = hist[tid * per + b];
            if (k < c + h) { *s_bin = tid * per + b; *s_krem = (int)(k - c); break; }
            c += h;
        }
    }
    __syncthreads();
}

// warp-aggregated histogram increment (values concentrated -> few atomics)
__device__ __forceinline__ void hist_add(unsigned* hist, unsigned bin, bool act) {
    unsigned key = act ? bin : 0xffffffffu;
    unsigned mm = __match_any_sync(0xffffffffu, key);
    if (act) {
        int leader = __ffs(mm) - 1;
        if ((threadIdx.x & 31) == leader)
            atomicAdd(&hist[bin], (unsigned)__popc(mm));
    }
}

// ---------------- K3: per-row exact radix select + thresholded sum -------------
__global__ void __launch_bounds__(256, 6) select_kernel(const int* __restrict__ stage_ptr,
                                                        int N, int rank) {
    __shared__ unsigned hist[2048];
    __shared__ unsigned s_warp[8];
    __shared__ int      s_bin, s_krem;
    __shared__ float    s_red[8];

    int x = blockIdx.x, tid = threadIdx.x;
    const float4* row4 = (const float4*)(g_S + (size_t)x * N);
    float v[16];
    #pragma unroll
    for (int j = 0; j < 4; ++j) {
        float4 t4 = row4[tid + 256 * j];
        v[4 * j + 0] = t4.x; v[4 * j + 1] = t4.y;
        v[4 * j + 2] = t4.z; v[4 * j + 3] = t4.w;
    }

    int stage = *stage_ptr;
    float ssum = 0.0f;

    if (stage) {
        // ---- L0: bits [31:21] ----
        #pragma unroll
        for (int i = 0; i < 8; ++i) hist[tid + 256 * i] = 0;
        __syncthreads();
        #pragma unroll
        for (int j = 0; j < 16; ++j)
            hist_add(hist, __float_as_uint(v[j]) >> 21, true);
        __syncthreads();
        locate_bin(hist, 2048, (unsigned)rank, s_warp, &s_bin, &s_krem);
        unsigned b0 = (unsigned)s_bin;
        unsigned k1 = (unsigned)s_krem;
        __syncthreads();

        // ---- L1: bits [20:10] within bin b0 ----
        #pragma unroll
        for (int i = 0; i < 8; ++i) hist[tid + 256 * i] = 0;
        __syncthreads();
        #pragma unroll
        for (int j = 0; j < 16; ++j) {
            unsigned key = __float_as_uint(v[j]);
            hist_add(hist, (key >> 10) & 2047u, (key >> 21) == b0);
        }
        __syncthreads();
        locate_bin(hist, 2048, k1, s_warp, &s_bin, &s_krem);
        unsigned b1 = (unsigned)s_bin;
        unsigned k2 = (unsigned)s_krem;
        unsigned p01 = (b0 << 11) | b1;
        __syncthreads();

        // ---- L2: bits [9:0] within prefix p01 ----
        #pragma unroll
        for (int i = 0; i < 4; ++i) hist[tid + 256 * i] = 0;
        __syncthreads();
        #pragma unroll
        for (int j = 0; j < 16; ++j) {
            unsigned key = __float_as_uint(v[j]);
            hist_add(hist, key & 1023u, (key >> 10) == p01);
        }
        __syncthreads();
        locate_bin(hist, 1024, k2, s_warp, &s_bin, &s_krem);
        unsigned b2 = (unsigned)s_bin;

        float t = __uint_as_float((b0 << 21) | (b1 << 10) | b2);  // exact rank-th value
        #pragma unroll
        for (int j = 0; j < 16; ++j)
            if (v[j] >= t) ssum += v[j];
    } else {
        #pragma unroll
        for (int j = 0; j < 16; ++j) ssum += v[j];
    }

    int lane = tid & 31, w = tid >> 5;
    #pragma unroll
    for (int o = 16; o; o >>= 1) ssum += __shfl_xor_sync(0xffffffffu, ssum, o);
    if (lane == 0) s_red[w] = ssum;
    __syncthreads();
    if (tid == 0) {
        float tot = 0.0f;
        #pragma unroll
        for (int ww = 0; ww < 8; ++ww) tot += s_red[ww];
        float pos = g_pos[x];
        g_loss[x] = -logf(pos / (pos + tot));
    }
}

// ---------------- K4: deterministic mean reduce --------------------------------
__global__ void reduce_kernel(float* __restrict__ out, int N) {
    __shared__ float s_red[8];
    int tid = threadIdx.x;
    float s = 0.0f;
    for (int i = tid; i < N; i += 256) s += g_loss[i];
    int lane = tid & 31, w = tid >> 5;
    #pragma unroll
    for (int o = 16; o; o >>= 1) s += __shfl_xor_sync(0xffffffffu, s, o);
    if (lane == 0) s_red[w] = s;
    __syncthreads();
    if (tid == 0) {
        float tot = 0.0f;
        #pragma unroll
        for (int ww = 0; ww < 8; ++ww) tot += s_red[ww];
        out[0] = tot / (float)N;
    }
}

// ---------------- launch --------------------------------------------------------
extern "C" void kernel_launch(void* const* d_in, const int* in_sizes, int n_in,
                              void* d_out, int out_size) {
    const float* emb   = (const float*)d_in[0];
    const int*   pp    = (const int*)d_in[1];
    const int*   stage = (const int*)d_in[2];

    int N      = in_sizes[0] / D;        // 4096
    int npairs = in_sizes[1] / 2;        // 4096

    build_q_kernel<<<(npairs + 255) / 256, 256>>>(pp, npairs);
    prep_kernel<<<N, D>>>(emb, N);

    int nb   = N >> 7;
    int nblk = nb * (nb + 1) / 2;
    int smem = 4 * 128 * KP * 2;         // 73728 bytes (staging reuses this)
    cudaFuncSetAttribute(gemm_wmma_kernel,
                         cudaFuncAttributeMaxDynamicSharedMemorySize, smem);
    gemm_wmma_kernel<<<nblk, 256, smem>>>(N);

    int rank = (int)(0.8 * (double)(N - 1) + 1e-9);   // 3276 for N=4096
    select_kernel<<<N, 256>>>(stage, N, rank);

    reduce_kernel<<<1, 256>>>((float*)d_out, N);
}

// round 8
// speedup vs baseline: 1.6894x; 1.6894x over previous
#include <cuda_runtime.h>
#include <cuda_bf16.h>
#include <mma.h>
#include <math.h>
#include <stdint.h>

using namespace nvcuda;

#define MAXN 4096
#define D    128

// ---------------- scratch (device globals; no allocation allowed) -------------
__device__ float         g_S[(size_t)MAXN * MAXN]; // exp(sim/tau), masked = 0
__device__ __nv_bfloat16 g_hn[MAXN * D];           // normalized hard_neg rows (bf16)
__device__ float         g_pos[MAXN];              // exp(cos(hp_x, hp_qx)/tau)
__device__ float         g_loss[MAXN];
__device__ int           g_q[MAXN];                // positive-pair partner

// ---------------- K0: build partner map ---------------------------------------
__global__ void build_q_kernel(const int* __restrict__ pp, int npairs) {
    int r = blockIdx.x * blockDim.x + threadIdx.x;
    if (r < npairs) g_q[pp[2 * r]] = pp[2 * r + 1];
}

// ---------------- K1: normalized hard_neg rows (bf16) + pos --------------------
__global__ void prep_kernel(const float* __restrict__ emb, int N) {
    int x = blockIdx.x;
    int d = threadIdx.x;
    int qx = g_q[x];
    int fx = N - 1;
    while (fx == x || fx == qx) fx--;   // largest index not in {x, q[x]}

    float a  = emb[(size_t)x  * D + d];
    float b  = emb[(size_t)qx * D + d];
    float pf = emb[(size_t)fx * D + d];
    float h  = 0.5f * (a + pf);

    float v0 = h * h, v1 = a * a, v2 = b * b, v3 = a * b;
    __shared__ float sh[4][4];
    int lane = d & 31, w = d >> 5;
    #pragma unroll
    for (int o = 16; o; o >>= 1) {
        v0 += __shfl_xor_sync(0xffffffffu, v0, o);
        v1 += __shfl_xor_sync(0xffffffffu, v1, o);
        v2 += __shfl_xor_sync(0xffffffffu, v2, o);
        v3 += __shfl_xor_sync(0xffffffffu, v3, o);
    }
    if (lane == 0) { sh[0][w] = v0; sh[1][w] = v1; sh[2][w] = v2; sh[3][w] = v3; }
    __syncthreads();
    float nn = sh[0][0] + sh[0][1] + sh[0][2] + sh[0][3];
    float inv = 1.0f / fmaxf(sqrtf(nn), 1e-8f);
    g_hn[(size_t)x * D + d] = __float2bfloat16(h * inv);

    if (d == 0) {
        float aa = sh[1][0] + sh[1][1] + sh[1][2] + sh[1][3];
        float bb = sh[2][0] + sh[2][1] + sh[2][2] + sh[2][3];
        float ab = sh[3][0] + sh[3][1] + sh[3][2] + sh[3][3];
        float dot = 2.5f * ab - 0.75f * (aa + bb);
        float nxx = 2.25f * aa + 0.25f * bb - 1.5f * ab;
        float nyy = 2.25f * bb + 0.25f * aa - 1.5f * ab;
        float nx = fmaxf(sqrtf(nxx), 1e-8f);
        float ny = fmaxf(sqrtf(nyy), 1e-8f);
        g_pos[x] = expf((dot / (nx * ny)) * 5.0f);
    }
}

// ---------------- K2: WMMA bf16 symmetric GEMM + exp + mask --------------------
// 128x128 tile per CTA, upper triangle only, mirror store. 256 threads, 8 warps.
// K in 2 chunks of 64, smem rows padded to 72 bf16 (conflict-free ldmatrix).
// NOTE: all wmma ldm values MUST be multiples of 16 bytes (KP=144B, LDS=528B).
#define KP  72
#define TSZ (128 * KP)       // bf16 elements per tile
#define LDS 132              // staging row stride (floats); 528B = 33*16B -> legal

__global__ void __launch_bounds__(256) gemm_wmma_kernel(int N) {
    extern __shared__ char smem[];
    __nv_bfloat16* Ah = (__nv_bfloat16*)smem;
    __nv_bfloat16* Bh = Ah + TSZ;
    float* Tst = (float*)smem;          // epilogue staging 128 x LDS (reuses tiles)

    int nb = N >> 7;
    int bid = blockIdx.x;
    int bi = 0, rem = bid;
    while (rem >= nb - bi) { rem -= nb - bi; bi++; }
    int bj = bi + rem;                  // bj >= bi

    int tid = threadIdx.x, wid = tid >> 5;
    int wm = wid >> 1, wn = wid & 1;    // warp tile: rows wm*32..+32, cols wn*64..+64

    wmma::fragment<wmma::accumulator, 16, 16, 16, float> acc[2][4];
    #pragma unroll
    for (int i = 0; i < 2; ++i)
        #pragma unroll
        for (int j = 0; j < 4; ++j) wmma::fill_fragment(acc[i][j], 0.0f);

    #pragma unroll
    for (int ch = 0; ch < 2; ++ch) {
        // load 2 tiles: 128 rows x 64 cols bf16 each, padded rows
        const __nv_bfloat16* srcA = g_hn + (size_t)bi * 128 * D + ch * 64;
        const __nv_bfloat16* srcB = g_hn + (size_t)bj * 128 * D + ch * 64;
        #pragma unroll
        for (int i = tid; i < 1024; i += 256) {   // 1024 uint4 per tile
            int row = i >> 3, c8 = i & 7;
            *(uint4*)(Ah + row * KP + c8 * 8) = *(const uint4*)(srcA + (size_t)row * D + c8 * 8);
            *(uint4*)(Bh + row * KP + c8 * 8) = *(const uint4*)(srcB + (size_t)row * D + c8 * 8);
        }
        __syncthreads();

        #pragma unroll
        for (int ks = 0; ks < 4; ++ks) {
            wmma::fragment<wmma::matrix_a, 16, 16, 16, __nv_bfloat16, wmma::row_major> a_f[2];
            wmma::fragment<wmma::matrix_b, 16, 16, 16, __nv_bfloat16, wmma::col_major> b_f[4];
            #pragma unroll
            for (int i = 0; i < 2; ++i)
                wmma::load_matrix_sync(a_f[i], Ah + (wm * 32 + i * 16) * KP + ks * 16, KP);
            #pragma unroll
            for (int j = 0; j < 4; ++j)
                wmma::load_matrix_sync(b_f[j], Bh + (wn * 64 + j * 16) * KP + ks * 16, KP);
            #pragma unroll
            for (int i = 0; i < 2; ++i)
                #pragma unroll
                for (int j = 0; j < 4; ++j)
                    wmma::mma_sync(acc[i][j], a_f[i], b_f[j], acc[i][j]);
        }
        __syncthreads();
    }

    // stage accumulators to smem (ldm = 132 floats = 528B, multiple of 16B)
    #pragma unroll
    for (int i = 0; i < 2; ++i)
        #pragma unroll
        for (int j = 0; j < 4; ++j)
            wmma::store_matrix_sync(Tst + (wm * 32 + i * 16) * LDS + wn * 64 + j * 16,
                                    acc[i][j], LDS, wmma::mem_row_major);
    __syncthreads();

    // mask + exp in place
    int m0 = bi * 128, n0 = bj * 128;
    for (int idx = tid; idx < 16384; idx += 256) {
        int r = idx >> 7, c = idx & 127;
        int m = m0 + r, n = n0 + c;
        float a = Tst[r * LDS + c];
        Tst[r * LDS + c] = (n == m || n == g_q[m]) ? 0.0f : __expf(a * 5.0f);
    }
    __syncthreads();

    // direct store: rows m0+r, coalesced cols
    int t = tid & 127, hseg = tid >> 7;
    #pragma unroll 4
    for (int j = 0; j < 64; ++j) {
        int r = j * 2 + hseg;
        g_S[(size_t)(m0 + r) * N + n0 + t] = Tst[r * LDS + t];
    }
    // mirror store: rows n0+c, coalesced cols at m0 (transposed smem read)
    #pragma unroll 4
    for (int j = 0; j < 64; ++j) {
        int c = j * 2 + hseg;
        g_S[(size_t)(n0 + c) * N + m0 + t] = Tst[t * LDS + c];
    }
}

// ---------------- K3 helper: locate bin containing rank k ----------------------
__device__ __forceinline__ void locate_bin(unsigned* hist, int nbins, unsigned k,
                                           unsigned* s_warp, int* s_bin, int* s_krem) {
    int tid = threadIdx.x;
    int per = nbins >> 8;
    unsigned local = 0;
    for (int b = 0; b < per; b++) local += hist[tid * per + b];
    unsigned inc = local;
    int lane = tid & 31, w = tid >> 5;
    #pragma unroll
    for (int o = 1; o < 32; o <<= 1) {
        unsigned t = __shfl_up_sync(0xffffffffu, inc, o);
        if (lane >= o) inc += t;
    }
    if (lane == 31) s_warp[w] = inc;
    __syncthreads();
    unsigned woff = 0;
    for (int ww = 0; ww < w; ++ww) woff += s_warp[ww];
    unsigned excl = woff + inc - local;
    if (excl <= k && k < excl + local) {
        unsigned c = excl;
        for (int b = 0; b < per; b++) {
            unsigned h = hist[tid * per + b];
            if (k < c + h) { *s_bin = tid * per + b; *s_krem = (int)(k - c); break; }
            c += h;
        }
    }
    __syncthreads();
}

// ---------------- K3: per-row exact radix select + thresholded sum -------------
// one CTA (256 threads) per row; 16 register values/thread; plain atomics;
// L0 histogram privatized into 2 copies (even/odd warp) then folded.
__global__ void __launch_bounds__(256) select_kernel(const int* __restrict__ stage_ptr,
                                                     int N, int rank) {
    __shared__ unsigned hist[4096];     // L0: two 2048 halves; L1/L2 use [0,2048)
    __shared__ unsigned s_warp[8];
    __shared__ int      s_bin, s_krem;
    __shared__ float    s_red[8];

    int x = blockIdx.x, tid = threadIdx.x;
    const float4* row4 = (const float4*)(g_S + (size_t)x * N);
    float v[16];
    #pragma unroll
    for (int j = 0; j < 4; ++j) {
        float4 t4 = row4[tid + 256 * j];
        v[4 * j + 0] = t4.x; v[4 * j + 1] = t4.y;
        v[4 * j + 2] = t4.z; v[4 * j + 3] = t4.w;
    }

    int stage = *stage_ptr;
    float ssum = 0.0f;

    if (stage) {
        unsigned hoff = ((tid >> 5) & 1) << 11;   // warp-parity histogram half
        // ---- L0: bits [31:21], dual histogram ----
        #pragma unroll
        for (int i = 0; i < 16; ++i) hist[tid + 256 * i] = 0;
        __syncthreads();
        #pragma unroll
        for (int j = 0; j < 16; ++j)
            atomicAdd(&hist[hoff + (__float_as_uint(v[j]) >> 21)], 1u);
        __syncthreads();
        for (int i = tid; i < 2048; i += 256) hist[i] += hist[i + 2048];
        __syncthreads();
        locate_bin(hist, 2048, (unsigned)rank, s_warp, &s_bin, &s_krem);
        unsigned b0 = (unsigned)s_bin;
        unsigned k1 = (unsigned)s_krem;
        __syncthreads();

        // ---- L1: bits [20:10] within bin b0 ----
        #pragma unroll
        for (int i = 0; i < 8; ++i) hist[tid + 256 * i] = 0;
        __syncthreads();
        #pragma unroll
        for (int j = 0; j < 16; ++j) {
            unsigned key = __float_as_uint(v[j]);
            if ((key >> 21) == b0)
                atomicAdd(&hist[(key >> 10) & 2047u], 1u);
        }
        __syncthreads();
        locate_bin(hist, 2048, k1, s_warp, &s_bin, &s_krem);
        unsigned b1 = (unsigned)s_bin;
        unsigned k2 = (unsigned)s_krem;
        unsigned p01 = (b0 << 11) | b1;
        __syncthreads();

        // ---- L2: bits [9:0] within prefix p01 ----
        #pragma unroll
        for (int i = 0; i < 4; ++i) hist[tid + 256 * i] = 0;
        __syncthreads();
        #pragma unroll
        for (int j = 0; j < 16; ++j) {
            unsigned key = __float_as_uint(v[j]);
            if ((key >> 10) == p01)
                atomicAdd(&hist[key & 1023u], 1u);
        }
        __syncthreads();
        locate_bin(hist, 1024, k2, s_warp, &s_bin, &s_krem);
        unsigned b2 = (unsigned)s_bin;

        float t = __uint_as_float((b0 << 21) | (b1 << 10) | b2);  // exact rank-th value
        #pragma unroll
        for (int j = 0; j < 16; ++j)
            if (v[j] >= t) ssum += v[j];
    } else {
        #pragma unroll
        for (int j = 0; j < 16; ++j) ssum += v[j];
    }

    int lane = tid & 31, w = tid >> 5;
    #pragma unroll
    for (int o = 16; o; o >>= 1) ssum += __shfl_xor_sync(0xffffffffu, ssum, o);
    if (lane == 0) s_red[w] = ssum;
    __syncthreads();
    if (tid == 0) {
        float tot = 0.0f;
        #pragma unroll
        for (int ww = 0; ww < 8; ++ww) tot += s_red[ww];
        float pos = g_pos[x];
        g_loss[x] = -logf(pos / (pos + tot));
    }
}

// ---------------- K4: deterministic mean reduce --------------------------------
__global__ void reduce_kernel(float* __restrict__ out, int N) {
    __shared__ float s_red[8];
    int tid = threadIdx.x;
    float s = 0.0f;
    for (int i = tid; i < N; i += 256) s += g_loss[i];
    int lane = tid & 31, w = tid >> 5;
    #pragma unroll
    for (int o = 16; o; o >>= 1) s += __shfl_xor_sync(0xffffffffu, s, o);
    if (lane == 0) s_red[w] = s;
    __syncthreads();
    if (tid == 0) {
        float tot = 0.0f;
        #pragma unroll
        for (int ww = 0; ww < 8; ++ww) tot += s_red[ww];
        out[0] = tot / (float)N;
    }
}

// ---------------- launch --------------------------------------------------------
extern "C" void kernel_launch(void* const* d_in, const int* in_sizes, int n_in,
                              void* d_out, int out_size) {
    const float* emb   = (const float*)d_in[0];
    const int*   pp    = (const int*)d_in[1];
    const int*   stage = (const int*)d_in[2];

    int N      = in_sizes[0] / D;        // 4096
    int npairs = in_sizes[1] / 2;        // 4096

    build_q_kernel<<<(npairs + 255) / 256, 256>>>(pp, npairs);
    prep_kernel<<<N, D>>>(emb, N);

    int nb   = N >> 7;
    int nblk = nb * (nb + 1) / 2;
    int smem = 128 * LDS * 4;            // 67584 bytes (tiles fit inside)
    cudaFuncSetAttribute(gemm_wmma_kernel,
                         cudaFuncAttributeMaxDynamicSharedMemorySize, smem);
    gemm_wmma_kernel<<<nblk, 256, smem>>>(N);

    int rank = (int)(0.8 * (double)(N - 1) + 1e-9);   // 3276 for N=4096
    select_kernel<<<N, 256>>>(stage, N, rank);

    reduce_kernel<<<1, 256>>>((float*)d_out, N);
}

// round 9
// speedup vs baseline: 1.9912x; 1.1787x over previous
#include <cuda_runtime.h>
#include <cuda_bf16.h>
#include <mma.h>
#include <math.h>
#include <stdint.h>

using namespace nvcuda;

#define MAXN 4096
#define D    128

// ---------------- scratch (device globals; no allocation allowed) -------------
__device__ __nv_bfloat16 g_S[(size_t)MAXN * MAXN]; // exp(sim/tau) in bf16, masked = 0
__device__ __nv_bfloat16 g_hn[MAXN * D];           // normalized hard_neg rows (bf16)
__device__ float         g_pos[MAXN];              // exp(cos(hp_x, hp_qx)/tau)
__device__ float         g_loss[MAXN];
__device__ int           g_q[MAXN];                // positive-pair partner

// ---------------- K0: build partner map ---------------------------------------
__global__ void build_q_kernel(const int* __restrict__ pp, int npairs) {
    int r = blockIdx.x * blockDim.x + threadIdx.x;
    if (r < npairs) g_q[pp[2 * r]] = pp[2 * r + 1];
}

// ---------------- K1: normalized hard_neg rows (bf16) + pos --------------------
__global__ void prep_kernel(const float* __restrict__ emb, int N) {
    int x = blockIdx.x;
    int d = threadIdx.x;
    int qx = g_q[x];
    int fx = N - 1;
    while (fx == x || fx == qx) fx--;   // largest index not in {x, q[x]}

    float a  = emb[(size_t)x  * D + d];
    float b  = emb[(size_t)qx * D + d];
    float pf = emb[(size_t)fx * D + d];
    float h  = 0.5f * (a + pf);

    float v0 = h * h, v1 = a * a, v2 = b * b, v3 = a * b;
    __shared__ float sh[4][4];
    int lane = d & 31, w = d >> 5;
    #pragma unroll
    for (int o = 16; o; o >>= 1) {
        v0 += __shfl_xor_sync(0xffffffffu, v0, o);
        v1 += __shfl_xor_sync(0xffffffffu, v1, o);
        v2 += __shfl_xor_sync(0xffffffffu, v2, o);
        v3 += __shfl_xor_sync(0xffffffffu, v3, o);
    }
    if (lane == 0) { sh[0][w] = v0; sh[1][w] = v1; sh[2][w] = v2; sh[3][w] = v3; }
    __syncthreads();
    float nn = sh[0][0] + sh[0][1] + sh[0][2] + sh[0][3];
    float inv = 1.0f / fmaxf(sqrtf(nn), 1e-8f);
    g_hn[(size_t)x * D + d] = __float2bfloat16(h * inv);

    if (d == 0) {
        float aa = sh[1][0] + sh[1][1] + sh[1][2] + sh[1][3];
        float bb = sh[2][0] + sh[2][1] + sh[2][2] + sh[2][3];
        float ab = sh[3][0] + sh[3][1] + sh[3][2] + sh[3][3];
        float dot = 2.5f * ab - 0.75f * (aa + bb);
        float nxx = 2.25f * aa + 0.25f * bb - 1.5f * ab;
        float nyy = 2.25f * bb + 0.25f * aa - 1.5f * ab;
        float nx = fmaxf(sqrtf(nxx), 1e-8f);
        float ny = fmaxf(sqrtf(nyy), 1e-8f);
        g_pos[x] = expf((dot / (nx * ny)) * 5.0f);
    }
}

// ---------------- K2: WMMA bf16 symmetric GEMM + exp + mask (bf16 out) ---------
// 128x128 tile per CTA, upper triangle only, mirror store. 256 threads, 8 warps.
// Mask predicate is symmetric (q is an involution), so both store orientations
// use (col==row || col==q[row]).
#define KP  72
#define TSZ (128 * KP)       // bf16 elements per tile
#define LDS 132              // staging row stride (floats); 528B = 33*16B -> legal

__global__ void __launch_bounds__(256) gemm_wmma_kernel(int N) {
    extern __shared__ char smem[];
    __nv_bfloat16* Ah = (__nv_bfloat16*)smem;
    __nv_bfloat16* Bh = Ah + TSZ;
    float* Tst = (float*)smem;          // epilogue staging 128 x LDS (reuses tiles)

    int nb = N >> 7;
    int bid = blockIdx.x;
    int bi = 0, rem = bid;
    while (rem >= nb - bi) { rem -= nb - bi; bi++; }
    int bj = bi + rem;                  // bj >= bi

    int tid = threadIdx.x, wid = tid >> 5;
    int wm = wid >> 1, wn = wid & 1;    // warp tile: rows wm*32..+32, cols wn*64..+64

    wmma::fragment<wmma::accumulator, 16, 16, 16, float> acc[2][4];
    #pragma unroll
    for (int i = 0; i < 2; ++i)
        #pragma unroll
        for (int j = 0; j < 4; ++j) wmma::fill_fragment(acc[i][j], 0.0f);

    #pragma unroll
    for (int ch = 0; ch < 2; ++ch) {
        const __nv_bfloat16* srcA = g_hn + (size_t)bi * 128 * D + ch * 64;
        const __nv_bfloat16* srcB = g_hn + (size_t)bj * 128 * D + ch * 64;
        #pragma unroll
        for (int i = tid; i < 1024; i += 256) {   // 1024 uint4 per tile
            int row = i >> 3, c8 = i & 7;
            *(uint4*)(Ah + row * KP + c8 * 8) = *(const uint4*)(srcA + (size_t)row * D + c8 * 8);
            *(uint4*)(Bh + row * KP + c8 * 8) = *(const uint4*)(srcB + (size_t)row * D + c8 * 8);
        }
        __syncthreads();

        #pragma unroll
        for (int ks = 0; ks < 4; ++ks) {
            wmma::fragment<wmma::matrix_a, 16, 16, 16, __nv_bfloat16, wmma::row_major> a_f[2];
            wmma::fragment<wmma::matrix_b, 16, 16, 16, __nv_bfloat16, wmma::col_major> b_f[4];
            #pragma unroll
            for (int i = 0; i < 2; ++i)
                wmma::load_matrix_sync(a_f[i], Ah + (wm * 32 + i * 16) * KP + ks * 16, KP);
            #pragma unroll
            for (int j = 0; j < 4; ++j)
                wmma::load_matrix_sync(b_f[j], Bh + (wn * 64 + j * 16) * KP + ks * 16, KP);
            #pragma unroll
            for (int i = 0; i < 2; ++i)
                #pragma unroll
                for (int j = 0; j < 4; ++j)
                    wmma::mma_sync(acc[i][j], a_f[i], b_f[j], acc[i][j]);
        }
        __syncthreads();
    }

    // stage raw accumulators to smem (ldm = 132 floats = 528B, multiple of 16B)
    #pragma unroll
    for (int i = 0; i < 2; ++i)
        #pragma unroll
        for (int j = 0; j < 4; ++j)
            wmma::store_matrix_sync(Tst + (wm * 32 + i * 16) * LDS + wn * 64 + j * 16,
                                    acc[i][j], LDS, wmma::mem_row_major);
    __syncthreads();

    int m0 = bi * 128, n0 = bj * 128;
    int t = tid & 127, hseg = tid >> 7;

    // direct store: rows m0+r, fused mask+exp, bf16 out (coalesced)
    #pragma unroll 4
    for (int j = 0; j < 64; ++j) {
        int r = j * 2 + hseg;
        int m = m0 + r, n = n0 + t;
        int qm = g_q[m];                              // broadcast load
        float a = Tst[r * LDS + t];
        float val = (n == m || n == qm) ? 0.0f : __expf(a * 5.0f);
        g_S[(size_t)m * N + n] = __float2bfloat16(val);
    }
    // mirror store: rows n0+c, cols m0+t (transposed smem read, coalesced gmem)
    #pragma unroll 4
    for (int j = 0; j < 64; ++j) {
        int c = j * 2 + hseg;
        int nrow = n0 + c, mcol = m0 + t;
        int qn = g_q[nrow];                           // broadcast load
        float a = Tst[t * LDS + c];
        float val = (mcol == nrow || mcol == qn) ? 0.0f : __expf(a * 5.0f);
        g_S[(size_t)nrow * N + mcol] = __float2bfloat16(val);
    }
}

// ---------------- K3 helper: locate bin containing rank k (256 bins) -----------
__device__ __forceinline__ void locate_bin256(unsigned* hist, unsigned k,
                                              unsigned* s_warp, int* s_bin, int* s_krem) {
    int tid = threadIdx.x;
    unsigned local = hist[tid];
    unsigned inc = local;
    int lane = tid & 31, w = tid >> 5;
    #pragma unroll
    for (int o = 1; o < 32; o <<= 1) {
        unsigned t = __shfl_up_sync(0xffffffffu, inc, o);
        if (lane >= o) inc += t;
    }
    if (lane == 31) s_warp[w] = inc;
    __syncthreads();
    unsigned woff = 0;
    for (int ww = 0; ww < w; ++ww) woff += s_warp[ww];
    unsigned excl = woff + inc - local;
    if (excl <= k && k < excl + local) { *s_bin = tid; *s_krem = (int)(k - excl); }
    __syncthreads();
}

// ---------------- K3: per-row exact radix select + thresholded sum (bf16) ------
// one CTA (256 threads) per row; 16 bf16 values/thread kept PACKED (8 u32 regs);
// 2-level radix on bf16 bits [15:8],[7:0], 8-way warp-privatized histograms.
__global__ void __launch_bounds__(256) select_kernel(const int* __restrict__ stage_ptr,
                                                     int N, int rank) {
    __shared__ unsigned hist[2048];     // 8 warp-private copies of 256 bins
    __shared__ unsigned s_warp[8];
    __shared__ int      s_bin, s_krem;
    __shared__ float    s_red[8];

    int x = blockIdx.x, tid = threadIdx.x, wid = tid >> 5;
    const uint4* row16 = (const uint4*)(g_S + (size_t)x * N);   // 8 bf16 per uint4
    uint4 p0 = row16[tid];
    uint4 p1 = row16[tid + 256];
    unsigned pk[8] = {p0.x, p0.y, p0.z, p0.w, p1.x, p1.y, p1.z, p1.w};

    int stage = *stage_ptr;
    float ssum = 0.0f;
    unsigned hbase = (unsigned)wid << 8;

    if (stage) {
        // ---- L0: bf16 bits [15:8] ----
        #pragma unroll
        for (int i = 0; i < 8; ++i) hist[tid + 256 * i] = 0;
        __syncthreads();
        #pragma unroll
        for (int r = 0; r < 8; ++r) {
            atomicAdd(&hist[hbase + ((pk[r] >> 8)  & 0xffu)], 1u);
            atomicAdd(&hist[hbase + ((pk[r] >> 24) & 0xffu)], 1u);
        }
        __syncthreads();
        {   // fold 8 copies
            unsigned s = 0;
            #pragma unroll
            for (int i = 0; i < 8; ++i) s += hist[tid + 256 * i];
            __syncthreads();
            hist[tid] = s;
        }
        __syncthreads();
        locate_bin256(hist, (unsigned)rank, s_warp, &s_bin, &s_krem);
        unsigned b0 = (unsigned)s_bin;
        unsigned k1 = (unsigned)s_krem;
        __syncthreads();

        // ---- L1: bf16 bits [7:0] within bin b0 ----
        #pragma unroll
        for (int i = 0; i < 8; ++i) hist[tid + 256 * i] = 0;
        __syncthreads();
        #pragma unroll
        for (int r = 0; r < 8; ++r) {
            unsigned lo = pk[r] & 0xffffu, hi = pk[r] >> 16;
            if ((lo >> 8) == b0) atomicAdd(&hist[hbase + (lo & 0xffu)], 1u);
            if ((hi >> 8) == b0) atomicAdd(&hist[hbase + (hi & 0xffu)], 1u);
        }
        __syncthreads();
        {
            unsigned s = 0;
            #pragma unroll
            for (int i = 0; i < 8; ++i) s += hist[tid + 256 * i];
            __syncthreads();
            hist[tid] = s;
        }
        __syncthreads();
        locate_bin256(hist, k1, s_warp, &s_bin, &s_krem);
        unsigned tbits = (b0 << 8) | (unsigned)s_bin;   // exact rank-th bf16 value

        #pragma unroll
        for (int r = 0; r < 8; ++r) {
            unsigned lo = pk[r] & 0xffffu, hi = pk[r] >> 16;
            if (lo >= tbits) ssum += __bfloat162float(__ushort_as_bfloat16((unsigned short)lo));
            if (hi >= tbits) ssum += __bfloat162float(__ushort_as_bfloat16((unsigned short)hi));
        }
    } else {
        #pragma unroll
        for (int r = 0; r < 8; ++r) {
            ssum += __bfloat162float(__ushort_as_bfloat16((unsigned short)(pk[r] & 0xffffu)));
            ssum += __bfloat162float(__ushort_as_bfloat16((unsigned short)(pk[r] >> 16)));
        }
    }

    int lane = tid & 31, w = tid >> 5;
    #pragma unroll
    for (int o = 16; o; o >>= 1) ssum += __shfl_xor_sync(0xffffffffu, ssum, o);
    if (lane == 0) s_red[w] = ssum;
    __syncthreads();
    if (tid == 0) {
        float tot = 0.0f;
        #pragma unroll
        for (int ww = 0; ww < 8; ++ww) tot += s_red[ww];
        float pos = g_pos[x];
        g_loss[x] = -logf(pos / (pos + tot));
    }
}

// ---------------- K4: deterministic mean reduce --------------------------------
__global__ void reduce_kernel(float* __restrict__ out, int N) {
    __shared__ float s_red[8];
    int tid = threadIdx.x;
    float s = 0.0f;
    for (int i = tid; i < N; i += 256) s += g_loss[i];
    int lane = tid & 31, w = tid >> 5;
    #pragma unroll
    for (int o = 16; o; o >>= 1) s += __shfl_xor_sync(0xffffffffu, s, o);
    if (lane == 0) s_red[w] = s;
    __syncthreads();
    if (tid == 0) {
        float tot = 0.0f;
        #pragma unroll
        for (int ww = 0; ww < 8; ++ww) tot += s_red[ww];
        out[0] = tot / (float)N;
    }
}

// ---------------- launch --------------------------------------------------------
extern "C" void kernel_launch(void* const* d_in, const int* in_sizes, int n_in,
                              void* d_out, int out_size) {
    const float* emb   = (const float*)d_in[0];
    const int*   pp    = (const int*)d_in[1];
    const int*   stage = (const int*)d_in[2];

    int N      = in_sizes[0] / D;        // 4096
    int npairs = in_sizes[1] / 2;        // 4096

    build_q_kernel<<<(npairs + 255) / 256, 256>>>(pp, npairs);
    prep_kernel<<<N, D>>>(emb, N);

    int nb   = N >> 7;
    int nblk = nb * (nb + 1) / 2;
    int smem = 128 * LDS * 4;            // 67584 bytes (bf16 tiles fit inside)
    cudaFuncSetAttribute(gemm_wmma_kernel,
                         cudaFuncAttributeMaxDynamicSharedMemorySize, smem);
    gemm_wmma_kernel<<<nblk, 256, smem>>>(N);

    int rank = (int)(0.8 * (double)(N - 1) + 1e-9);   // 3276 for N=4096
    select_kernel<<<N, 256>>>(stage, N, rank);

    reduce_kernel<<<1, 256>>>((float*)d_out, N);
}

// round 10
// speedup vs baseline: 2.2448x; 1.1274x over previous
#include <cuda_runtime.h>
#include <cuda_bf16.h>
#include <cuda_fp16.h>
#include <mma.h>
#include <math.h>
#include <stdint.h>

using namespace nvcuda;

#define MAXN 4096
#define D    128

// ---------------- scratch (device globals; no allocation allowed) -------------
__device__ __half        g_S[(size_t)MAXN * MAXN]; // exp(sim/tau) in fp16, masked = 0
__device__ __nv_bfloat16 g_hn[MAXN * D];           // normalized hard_neg rows (bf16)
__device__ float         g_pos[MAXN];              // exp(cos(hp_x, hp_qx)/tau)
__device__ float         g_loss[MAXN];
__device__ int           g_q[MAXN];                // positive-pair partner

// ---------------- K0: build partner map ---------------------------------------
__global__ void build_q_kernel(const int* __restrict__ pp, int npairs) {
    int r = blockIdx.x * blockDim.x + threadIdx.x;
    if (r < npairs) g_q[pp[2 * r]] = pp[2 * r + 1];
}

// ---------------- K1: normalized hard_neg rows (bf16) + pos --------------------
__global__ void prep_kernel(const float* __restrict__ emb, int N) {
    int x = blockIdx.x;
    int d = threadIdx.x;
    int qx = g_q[x];
    int fx = N - 1;
    while (fx == x || fx == qx) fx--;   // largest index not in {x, q[x]}

    float a  = emb[(size_t)x  * D + d];
    float b  = emb[(size_t)qx * D + d];
    float pf = emb[(size_t)fx * D + d];
    float h  = 0.5f * (a + pf);

    float v0 = h * h, v1 = a * a, v2 = b * b, v3 = a * b;
    __shared__ float sh[4][4];
    int lane = d & 31, w = d >> 5;
    #pragma unroll
    for (int o = 16; o; o >>= 1) {
        v0 += __shfl_xor_sync(0xffffffffu, v0, o);
        v1 += __shfl_xor_sync(0xffffffffu, v1, o);
        v2 += __shfl_xor_sync(0xffffffffu, v2, o);
        v3 += __shfl_xor_sync(0xffffffffu, v3, o);
    }
    if (lane == 0) { sh[0][w] = v0; sh[1][w] = v1; sh[2][w] = v2; sh[3][w] = v3; }
    __syncthreads();
    float nn = sh[0][0] + sh[0][1] + sh[0][2] + sh[0][3];
    float inv = 1.0f / fmaxf(sqrtf(nn), 1e-8f);
    g_hn[(size_t)x * D + d] = __float2bfloat16(h * inv);

    if (d == 0) {
        float aa = sh[1][0] + sh[1][1] + sh[1][2] + sh[1][3];
        float bb = sh[2][0] + sh[2][1] + sh[2][2] + sh[2][3];
        float ab = sh[3][0] + sh[3][1] + sh[3][2] + sh[3][3];
        float dot = 2.5f * ab - 0.75f * (aa + bb);
        float nxx = 2.25f * aa + 0.25f * bb - 1.5f * ab;
        float nyy = 2.25f * bb + 0.25f * aa - 1.5f * ab;
        float nx = fmaxf(sqrtf(nxx), 1e-8f);
        float ny = fmaxf(sqrtf(nyy), 1e-8f);
        g_pos[x] = expf((dot / (nx * ny)) * 5.0f);
    }
}

// ---------------- K2: WMMA bf16 GEMM + exp + mask (fp16 out, FULL tiles) -------
// 128x128 tile per CTA, ALL nb*nb tiles (no mirror -> no transposed smem read).
// 256 threads, 8 warps. Epilogue: float4 smem read -> 4x mask+exp -> STG.64.
#define KP  72
#define TSZ (128 * KP)       // bf16 elements per tile
#define LDS 132              // staging row stride (floats); 528B = 33*16B -> legal

__global__ void __launch_bounds__(256) gemm_wmma_kernel(int N) {
    extern __shared__ char smem[];
    __nv_bfloat16* Ah = (__nv_bfloat16*)smem;
    __nv_bfloat16* Bh = Ah + TSZ;
    float* Tst = (float*)smem;          // epilogue staging 128 x LDS (reuses tiles)
    __shared__ int s_qa[128];

    int nb = N >> 7;
    int bid = blockIdx.x;
    int bi = bid / nb, bj = bid - bi * nb;
    int m0 = bi * 128, n0 = bj * 128;

    int tid = threadIdx.x, wid = tid >> 5;
    int wm = wid >> 1, wn = wid & 1;    // warp tile: rows wm*32..+32, cols wn*64..+64

    if (tid < 128) s_qa[tid] = g_q[m0 + tid];

    wmma::fragment<wmma::accumulator, 16, 16, 16, float> acc[2][4];
    #pragma unroll
    for (int i = 0; i < 2; ++i)
        #pragma unroll
        for (int j = 0; j < 4; ++j) wmma::fill_fragment(acc[i][j], 0.0f);

    #pragma unroll
    for (int ch = 0; ch < 2; ++ch) {
        const __nv_bfloat16* srcA = g_hn + (size_t)bi * 128 * D + ch * 64;
        const __nv_bfloat16* srcB = g_hn + (size_t)bj * 128 * D + ch * 64;
        #pragma unroll
        for (int i = tid; i < 1024; i += 256) {   // 1024 uint4 per tile
            int row = i >> 3, c8 = i & 7;
            *(uint4*)(Ah + row * KP + c8 * 8) = *(const uint4*)(srcA + (size_t)row * D + c8 * 8);
            *(uint4*)(Bh + row * KP + c8 * 8) = *(const uint4*)(srcB + (size_t)row * D + c8 * 8);
        }
        __syncthreads();

        #pragma unroll
        for (int ks = 0; ks < 4; ++ks) {
            wmma::fragment<wmma::matrix_a, 16, 16, 16, __nv_bfloat16, wmma::row_major> a_f[2];
            wmma::fragment<wmma::matrix_b, 16, 16, 16, __nv_bfloat16, wmma::col_major> b_f[4];
            #pragma unroll
            for (int i = 0; i < 2; ++i)
                wmma::load_matrix_sync(a_f[i], Ah + (wm * 32 + i * 16) * KP + ks * 16, KP);
            #pragma unroll
            for (int j = 0; j < 4; ++j)
                wmma::load_matrix_sync(b_f[j], Bh + (wn * 64 + j * 16) * KP + ks * 16, KP);
            #pragma unroll
            for (int i = 0; i < 2; ++i)
                #pragma unroll
                for (int j = 0; j < 4; ++j)
                    wmma::mma_sync(acc[i][j], a_f[i], b_f[j], acc[i][j]);
        }
        __syncthreads();
    }

    // stage raw accumulators to smem (ldm = 132 floats = 528B, multiple of 16B)
    #pragma unroll
    for (int i = 0; i < 2; ++i)
        #pragma unroll
        for (int j = 0; j < 4; ++j)
            wmma::store_matrix_sync(Tst + (wm * 32 + i * 16) * LDS + wn * 64 + j * 16,
                                    acc[i][j], LDS, wmma::mem_row_major);
    __syncthreads();

    // fused mask + exp + fp16 pack + vector store (STG.64, 256B/warp coalesced)
    int l = tid & 31;                   // column group: cols n0 + 4l .. 4l+3
    #pragma unroll
    for (int it = 0; it < 16; ++it) {
        int r = wid + 8 * it;           // 0..127
        float4 a4 = *(const float4*)(Tst + r * LDS + 4 * l);
        int m = m0 + r, qm = s_qa[r];
        int n = n0 + 4 * l;
        float f0 = (n     == m || n     == qm) ? 0.0f : __expf(a4.x * 5.0f);
        float f1 = (n + 1 == m || n + 1 == qm) ? 0.0f : __expf(a4.y * 5.0f);
        float f2 = (n + 2 == m || n + 2 == qm) ? 0.0f : __expf(a4.z * 5.0f);
        float f3 = (n + 3 == m || n + 3 == qm) ? 0.0f : __expf(a4.w * 5.0f);
        __half2 h01 = __floats2half2_rn(f0, f1);
        __half2 h23 = __floats2half2_rn(f2, f3);
        uint2 pkv;
        pkv.x = *(unsigned*)&h01;
        pkv.y = *(unsigned*)&h23;
        *(uint2*)(g_S + (size_t)m * N + n) = pkv;
    }
}

// ---------------- K3 helper: locate bin containing rank k (256 bins) -----------
__device__ __forceinline__ void locate_bin256(unsigned* hist, unsigned k,
                                              unsigned* s_warp, int* s_bin, int* s_krem) {
    int tid = threadIdx.x;
    unsigned local = hist[tid];
    unsigned inc = local;
    int lane = tid & 31, w = tid >> 5;
    #pragma unroll
    for (int o = 1; o < 32; o <<= 1) {
        unsigned t = __shfl_up_sync(0xffffffffu, inc, o);
        if (lane >= o) inc += t;
    }
    if (lane == 31) s_warp[w] = inc;
    __syncthreads();
    unsigned woff = 0;
    for (int ww = 0; ww < w; ++ww) woff += s_warp[ww];
    unsigned excl = woff + inc - local;
    if (excl <= k && k < excl + local) { *s_bin = tid; *s_krem = (int)(k - excl); }
    __syncthreads();
}

// ---------------- K3: per-row exact radix select + thresholded sum (fp16) ------
// one CTA (256 threads) per row; 16 fp16 values/thread kept PACKED (8 u32 regs);
// 2-level radix on fp16 bits [15:8],[7:0], 8-way warp-privatized histograms.
__global__ void __launch_bounds__(256) select_kernel(const int* __restrict__ stage_ptr,
                                                     int N, int rank) {
    __shared__ unsigned hist[2048];     // 8 warp-private copies of 256 bins
    __shared__ unsigned s_warp[8];
    __shared__ int      s_bin, s_krem;
    __shared__ float    s_red[8];

    int x = blockIdx.x, tid = threadIdx.x, wid = tid >> 5;
    const uint4* row16 = (const uint4*)(g_S + (size_t)x * N);   // 8 fp16 per uint4
    uint4 p0 = row16[tid];
    uint4 p1 = row16[tid + 256];
    unsigned pk[8] = {p0.x, p0.y, p0.z, p0.w, p1.x, p1.y, p1.z, p1.w};

    int stage = *stage_ptr;
    float ssum = 0.0f;
    unsigned hbase = (unsigned)wid << 8;

    if (stage) {
        // ---- L0: fp16 bits [15:8] ----
        #pragma unroll
        for (int i = 0; i < 8; ++i) hist[tid + 256 * i] = 0;
        __syncthreads();
        #pragma unroll
        for (int r = 0; r < 8; ++r) {
            atomicAdd(&hist[hbase + ((pk[r] >> 8)  & 0xffu)], 1u);
            atomicAdd(&hist[hbase + ((pk[r] >> 24) & 0xffu)], 1u);
        }
        __syncthreads();
        {   // fold 8 copies
            unsigned s = 0;
            #pragma unroll
            for (int i = 0; i < 8; ++i) s += hist[tid + 256 * i];
            __syncthreads();
            hist[tid] = s;
        }
        __syncthreads();
        locate_bin256(hist, (unsigned)rank, s_warp, &s_bin, &s_krem);
        unsigned b0 = (unsigned)s_bin;
        unsigned k1 = (unsigned)s_krem;
        __syncthreads();

        // ---- L1: fp16 bits [7:0] within bin b0 ----
        #pragma unroll
        for (int i = 0; i < 8; ++i) hist[tid + 256 * i] = 0;
        __syncthreads();
        #pragma unroll
        for (int r = 0; r < 8; ++r) {
            unsigned lo = pk[r] & 0xffffu, hi = pk[r] >> 16;
            if ((lo >> 8) == b0) atomicAdd(&hist[hbase + (lo & 0xffu)], 1u);
            if ((hi >> 8) == b0) atomicAdd(&hist[hbase + (hi & 0xffu)], 1u);
        }
        __syncthreads();
        {
            unsigned s = 0;
            #pragma unroll
            for (int i = 0; i < 8; ++i) s += hist[tid + 256 * i];
            __syncthreads();
            hist[tid] = s;
        }
        __syncthreads();
        locate_bin256(hist, k1, s_warp, &s_bin, &s_krem);
        unsigned tbits = (b0 << 8) | (unsigned)s_bin;   // exact rank-th fp16 value

        #pragma unroll
        for (int r = 0; r < 8; ++r) {
            unsigned lo = pk[r] & 0xffffu, hi = pk[r] >> 16;
            if (lo >= tbits) ssum += __half2float(__ushort_as_half((unsigned short)lo));
            if (hi >= tbits) ssum += __half2float(__ushort_as_half((unsigned short)hi));
        }
    } else {
        #pragma unroll
        for (int r = 0; r < 8; ++r) {
            ssum += __half2float(__ushort_as_half((unsigned short)(pk[r] & 0xffffu)));
            ssum += __half2float(__ushort_as_half((unsigned short)(pk[r] >> 16)));
        }
    }

    int lane = tid & 31, w = tid >> 5;
    #pragma unroll
    for (int o = 16; o; o >>= 1) ssum += __shfl_xor_sync(0xffffffffu, ssum, o);
    if (lane == 0) s_red[w] = ssum;
    __syncthreads();
    if (tid == 0) {
        float tot = 0.0f;
        #pragma unroll
        for (int ww = 0; ww < 8; ++ww) tot += s_red[ww];
        float pos = g_pos[x];
        g_loss[x] = -logf(pos / (pos + tot));
    }
}

// ---------------- K4: deterministic mean reduce --------------------------------
__global__ void reduce_kernel(float* __restrict__ out, int N) {
    __shared__ float s_red[8];
    int tid = threadIdx.x;
    float s = 0.0f;
    for (int i = tid; i < N; i += 256) s += g_loss[i];
    int lane = tid & 31, w = tid >> 5;
    #pragma unroll
    for (int o = 16; o; o >>= 1) s += __shfl_xor_sync(0xffffffffu, s, o);
    if (lane == 0) s_red[w] = s;
    __syncthreads();
    if (tid == 0) {
        float tot = 0.0f;
        #pragma unroll
        for (int ww = 0; ww < 8; ++ww) tot += s_red[ww];
        out[0] = tot / (float)N;
    }
}

// ---------------- launch --------------------------------------------------------
extern "C" void kernel_launch(void* const* d_in, const int* in_sizes, int n_in,
                              void* d_out, int out_size) {
    const float* emb   = (const float*)d_in[0];
    const int*   pp    = (const int*)d_in[1];
    const int*   stage = (const int*)d_in[2];

    int N      = in_sizes[0] / D;        // 4096
    int npairs = in_sizes[1] / 2;        // 4096

    build_q_kernel<<<(npairs + 255) / 256, 256>>>(pp, npairs);
    prep_kernel<<<N, D>>>(emb, N);

    int nb   = N >> 7;
    int nblk = nb * nb;                  // full tiles, no mirror
    int smem = 128 * LDS * 4;            // 67584 bytes (bf16 tiles fit inside)
    cudaFuncSetAttribute(gemm_wmma_kernel,
                         cudaFuncAttributeMaxDynamicSharedMemorySize, smem);
    gemm_wmma_kernel<<<nblk, 256, smem>>>(N);

    int rank = (int)(0.8 * (double)(N - 1) + 1e-9);   // 3276 for N=4096
    select_kernel<<<N, 256>>>(stage, N, rank);

    reduce_kernel<<<1, 256>>>((float*)d_out, N);
}

// round 11
// speedup vs baseline: 2.3795x; 1.0600x over previous
#include <cuda_runtime.h>
#include <cuda_bf16.h>
#include <cuda_fp16.h>
#include <mma.h>
#include <math.h>
#include <stdint.h>

using namespace nvcuda;

#define MAXN 4096
#define D    128

// ---------------- scratch (device globals; no allocation allowed) -------------
__device__ __half        g_S[(size_t)MAXN * MAXN]; // exp(sim/tau) in fp16, masked = 0
__device__ __nv_bfloat16 g_hn[MAXN * D];           // normalized hard_neg rows (bf16)
__device__ float         g_pos[MAXN];              // exp(cos(hp_x, hp_qx)/tau)
__device__ float         g_loss[MAXN];
__device__ int           g_q[MAXN];                // positive-pair partner

// ---------------- K0: build partner map ---------------------------------------
__global__ void build_q_kernel(const int* __restrict__ pp, int npairs) {
    int r = blockIdx.x * blockDim.x + threadIdx.x;
    if (r < npairs) g_q[pp[2 * r]] = pp[2 * r + 1];
}

// ---------------- K1: normalized hard_neg rows (bf16) + pos --------------------
__global__ void prep_kernel(const float* __restrict__ emb, int N) {
    int x = blockIdx.x;
    int d = threadIdx.x;
    int qx = g_q[x];
    int fx = N - 1;
    while (fx == x || fx == qx) fx--;   // largest index not in {x, q[x]}

    float a  = emb[(size_t)x  * D + d];
    float b  = emb[(size_t)qx * D + d];
    float pf = emb[(size_t)fx * D + d];
    float h  = 0.5f * (a + pf);

    float v0 = h * h, v1 = a * a, v2 = b * b, v3 = a * b;
    __shared__ float sh[4][4];
    int lane = d & 31, w = d >> 5;
    #pragma unroll
    for (int o = 16; o; o >>= 1) {
        v0 += __shfl_xor_sync(0xffffffffu, v0, o);
        v1 += __shfl_xor_sync(0xffffffffu, v1, o);
        v2 += __shfl_xor_sync(0xffffffffu, v2, o);
        v3 += __shfl_xor_sync(0xffffffffu, v3, o);
    }
    if (lane == 0) { sh[0][w] = v0; sh[1][w] = v1; sh[2][w] = v2; sh[3][w] = v3; }
    __syncthreads();
    float nn = sh[0][0] + sh[0][1] + sh[0][2] + sh[0][3];
    float inv = 1.0f / fmaxf(sqrtf(nn), 1e-8f);
    g_hn[(size_t)x * D + d] = __float2bfloat16(h * inv);

    if (d == 0) {
        float aa = sh[1][0] + sh[1][1] + sh[1][2] + sh[1][3];
        float bb = sh[2][0] + sh[2][1] + sh[2][2] + sh[2][3];
        float ab = sh[3][0] + sh[3][1] + sh[3][2] + sh[3][3];
        float dot = 2.5f * ab - 0.75f * (aa + bb);
        float nxx = 2.25f * aa + 0.25f * bb - 1.5f * ab;
        float nyy = 2.25f * bb + 0.25f * aa - 1.5f * ab;
        float nx = fmaxf(sqrtf(nxx), 1e-8f);
        float ny = fmaxf(sqrtf(nyy), 1e-8f);
        g_pos[x] = expf((dot / (nx * ny)) * 5.0f);
    }
}

// ---------------- K2: WMMA bf16 GEMM + exp + mask (fp16 out, TRIANGLE) ---------
// 128x128 tile per CTA, upper triangle only (528 CTAs), mirror store.
// Mask+exp applied ONCE in-place on fp32 staging (predicate symmetric under q).
// Direct store: row-contiguous fp32 read -> 8x cvt -> STG.128.
// Mirror store: column gather (lane-consecutive words, conflict-free) -> STG.128.
#define KP  72
#define TSZ (128 * KP)       // bf16 elements per tile
#define LDS 132              // staging row stride (floats); 528B = 33*16B -> legal

__global__ void __launch_bounds__(256) gemm_wmma_kernel(int N) {
    extern __shared__ char smem[];
    __nv_bfloat16* Ah = (__nv_bfloat16*)smem;
    __nv_bfloat16* Bh = Ah + TSZ;
    float* Tst = (float*)smem;          // epilogue staging 128 x LDS (reuses tiles)
    __shared__ int s_qa[128];

    int nb = N >> 7;
    int bid = blockIdx.x;
    int bi = 0, rem = bid;
    while (rem >= nb - bi) { rem -= nb - bi; bi++; }
    int bj = bi + rem;                  // bj >= bi
    int m0 = bi * 128, n0 = bj * 128;

    int tid = threadIdx.x, wid = tid >> 5;
    int wm = wid >> 1, wn = wid & 1;    // warp tile: rows wm*32..+32, cols wn*64..+64

    if (tid < 128) s_qa[tid] = g_q[m0 + tid];

    wmma::fragment<wmma::accumulator, 16, 16, 16, float> acc[2][4];
    #pragma unroll
    for (int i = 0; i < 2; ++i)
        #pragma unroll
        for (int j = 0; j < 4; ++j) wmma::fill_fragment(acc[i][j], 0.0f);

    #pragma unroll
    for (int ch = 0; ch < 2; ++ch) {
        const __nv_bfloat16* srcA = g_hn + (size_t)bi * 128 * D + ch * 64;
        const __nv_bfloat16* srcB = g_hn + (size_t)bj * 128 * D + ch * 64;
        #pragma unroll
        for (int i = tid; i < 1024; i += 256) {   // 1024 uint4 per tile
            int row = i >> 3, c8 = i & 7;
            *(uint4*)(Ah + row * KP + c8 * 8) = *(const uint4*)(srcA + (size_t)row * D + c8 * 8);
            *(uint4*)(Bh + row * KP + c8 * 8) = *(const uint4*)(srcB + (size_t)row * D + c8 * 8);
        }
        __syncthreads();

        #pragma unroll
        for (int ks = 0; ks < 4; ++ks) {
            wmma::fragment<wmma::matrix_a, 16, 16, 16, __nv_bfloat16, wmma::row_major> a_f[2];
            wmma::fragment<wmma::matrix_b, 16, 16, 16, __nv_bfloat16, wmma::col_major> b_f[4];
            #pragma unroll
            for (int i = 0; i < 2; ++i)
                wmma::load_matrix_sync(a_f[i], Ah + (wm * 32 + i * 16) * KP + ks * 16, KP);
            #pragma unroll
            for (int j = 0; j < 4; ++j)
                wmma::load_matrix_sync(b_f[j], Bh + (wn * 64 + j * 16) * KP + ks * 16, KP);
            #pragma unroll
            for (int i = 0; i < 2; ++i)
                #pragma unroll
                for (int j = 0; j < 4; ++j)
                    wmma::mma_sync(acc[i][j], a_f[i], b_f[j], acc[i][j]);
        }
        __syncthreads();
    }

    // stage raw accumulators to smem (ldm = 132 floats = 528B, multiple of 16B)
    #pragma unroll
    for (int i = 0; i < 2; ++i)
        #pragma unroll
        for (int j = 0; j < 4; ++j)
            wmma::store_matrix_sync(Tst + (wm * 32 + i * 16) * LDS + wn * 64 + j * 16,
                                    acc[i][j], LDS, wmma::mem_row_major);
    __syncthreads();

    // mask + exp in place (once; predicate symmetric: n==q[m] <=> m==q[n])
    #pragma unroll 4
    for (int idx = tid; idx < 16384; idx += 256) {
        int r = idx >> 7, c = idx & 127;
        int m = m0 + r, n = n0 + c;
        float a = Tst[r * LDS + c];
        Tst[r * LDS + c] = (n == m || n == s_qa[r]) ? 0.0f : __expf(a * 5.0f);
    }
    __syncthreads();

    // direct store: thread -> 8 consecutive cols of one row, STG.128
    {
        int rbase = tid >> 4;            // 0..15
        int c8 = (tid & 15) * 8;         // 0,8,..,120
        #pragma unroll
        for (int p = 0; p < 8; ++p) {
            int r = p * 16 + rbase;
            const float* src = Tst + r * LDS + c8;
            float4 a0 = *(const float4*)(src);
            float4 a1 = *(const float4*)(src + 4);
            __half2 h0 = __floats2half2_rn(a0.x, a0.y);
            __half2 h1 = __floats2half2_rn(a0.z, a0.w);
            __half2 h2 = __floats2half2_rn(a1.x, a1.y);
            __half2 h3 = __floats2half2_rn(a1.z, a1.w);
            uint4 pkv = make_uint4(*(unsigned*)&h0, *(unsigned*)&h1,
                                   *(unsigned*)&h2, *(unsigned*)&h3);
            *(uint4*)(g_S + (size_t)(m0 + r) * N + n0 + c8) = pkv;
        }
    }
    // mirror store: thread owns staging column c; gathers 8 rows -> STG.128
    // (lane-consecutive word reads: conflict-free)
    {
        int c    = tid & 127;
        int hseg = tid >> 7;             // 0/1 -> r halves
        #pragma unroll
        for (int j = 0; j < 8; ++j) {
            int r0 = hseg * 64 + j * 8;
            float f[8];
            #pragma unroll
            for (int k = 0; k < 8; ++k) f[k] = Tst[(r0 + k) * LDS + c];
            __half2 h0 = __floats2half2_rn(f[0], f[1]);
            __half2 h1 = __floats2half2_rn(f[2], f[3]);
            __half2 h2 = __floats2half2_rn(f[4], f[5]);
            __half2 h3 = __floats2half2_rn(f[6], f[7]);
            uint4 pkv = make_uint4(*(unsigned*)&h0, *(unsigned*)&h1,
                                   *(unsigned*)&h2, *(unsigned*)&h3);
            *(uint4*)(g_S + (size_t)(n0 + c) * N + m0 + r0) = pkv;
        }
    }
}

// ---------------- K3 helper: locate bin containing rank k (256 bins) -----------
__device__ __forceinline__ void locate_bin256(unsigned* hist, unsigned k,
                                              unsigned* s_warp, int* s_bin, int* s_krem) {
    int tid = threadIdx.x;
    unsigned local = hist[tid];
    unsigned inc = local;
    int lane = tid & 31, w = tid >> 5;
    #pragma unroll
    for (int o = 1; o < 32; o <<= 1) {
        unsigned t = __shfl_up_sync(0xffffffffu, inc, o);
        if (lane >= o) inc += t;
    }
    if (lane == 31) s_warp[w] = inc;
    __syncthreads();
    unsigned woff = 0;
    for (int ww = 0; ww < w; ++ww) woff += s_warp[ww];
    unsigned excl = woff + inc - local;
    if (excl <= k && k < excl + local) { *s_bin = tid; *s_krem = (int)(k - excl); }
    __syncthreads();
}

// ---------------- K3: per-row exact radix select + thresholded sum (fp16) ------
// one CTA (256 threads) per row; 16 fp16 values/thread kept PACKED (8 u32 regs);
// 2-level radix on fp16 bits [15:8],[7:0], 8-way warp-privatized histograms.
__global__ void __launch_bounds__(256) select_kernel(const int* __restrict__ stage_ptr,
                                                     int N, int rank) {
    __shared__ unsigned hist[2048];     // 8 warp-private copies of 256 bins
    __shared__ unsigned s_warp[8];
    __shared__ int      s_bin, s_krem;
    __shared__ float    s_red[8];

    int x = blockIdx.x, tid = threadIdx.x, wid = tid >> 5;
    const uint4* row16 = (const uint4*)(g_S + (size_t)x * N);   // 8 fp16 per uint4
    uint4 p0 = row16[tid];
    uint4 p1 = row16[tid + 256];
    unsigned pk[8] = {p0.x, p0.y, p0.z, p0.w, p1.x, p1.y, p1.z, p1.w};

    int stage = *stage_ptr;
    float ssum = 0.0f;
    unsigned hbase = (unsigned)wid << 8;

    if (stage) {
        // ---- L0: fp16 bits [15:8] ----
        #pragma unroll
        for (int i = 0; i < 8; ++i) hist[tid + 256 * i] = 0;
        __syncthreads();
        #pragma unroll
        for (int r = 0; r < 8; ++r) {
            atomicAdd(&hist[hbase + ((pk[r] >> 8)  & 0xffu)], 1u);
            atomicAdd(&hist[hbase + ((pk[r] >> 24) & 0xffu)], 1u);
        }
        __syncthreads();
        {   // fold 8 copies
            unsigned s = 0;
            #pragma unroll
            for (int i = 0; i < 8; ++i) s += hist[tid + 256 * i];
            __syncthreads();
            hist[tid] = s;
        }
        __syncthreads();
        locate_bin256(hist, (unsigned)rank, s_warp, &s_bin, &s_krem);
        unsigned b0 = (unsigned)s_bin;
        unsigned k1 = (unsigned)s_krem;
        __syncthreads();

        // ---- L1: fp16 bits [7:0] within bin b0 ----
        #pragma unroll
        for (int i = 0; i < 8; ++i) hist[tid + 256 * i] = 0;
        __syncthreads();
        #pragma unroll
        for (int r = 0; r < 8; ++r) {
            unsigned lo = pk[r] & 0xffffu, hi = pk[r] >> 16;
            if ((lo >> 8) == b0) atomicAdd(&hist[hbase + (lo & 0xffu)], 1u);
            if ((hi >> 8) == b0) atomicAdd(&hist[hbase + (hi & 0xffu)], 1u);
        }
        __syncthreads();
        {
            unsigned s = 0;
            #pragma unroll
            for (int i = 0; i < 8; ++i) s += hist[tid + 256 * i];
            __syncthreads();
            hist[tid] = s;
        }
        __syncthreads();
        locate_bin256(hist, k1, s_warp, &s_bin, &s_krem);
        unsigned tbits = (b0 << 8) | (unsigned)s_bin;   // exact rank-th fp16 value

        #pragma unroll
        for (int r = 0; r < 8; ++r) {
            unsigned lo = pk[r] & 0xffffu, hi = pk[r] >> 16;
            if (lo >= tbits) ssum += __half2float(__ushort_as_half((unsigned short)lo));
            if (hi >= tbits) ssum += __half2float(__ushort_as_half((unsigned short)hi));
        }
    } else {
        #pragma unroll
        for (int r = 0; r < 8; ++r) {
            ssum += __half2float(__ushort_as_half((unsigned short)(pk[r] & 0xffffu)));
            ssum += __half2float(__ushort_as_half((unsigned short)(pk[r] >> 16)));
        }
    }

    int lane = tid & 31, w = tid >> 5;
    #pragma unroll
    for (int o = 16; o; o >>= 1) ssum += __shfl_xor_sync(0xffffffffu, ssum, o);
    if (lane == 0) s_red[w] = ssum;
    __syncthreads();
    if (tid == 0) {
        float tot = 0.0f;
        #pragma unroll
        for (int ww = 0; ww < 8; ++ww) tot += s_red[ww];
        float pos = g_pos[x];
        g_loss[x] = -logf(pos / (pos + tot));
    }
}

// ---------------- K4: deterministic mean reduce --------------------------------
__global__ void reduce_kernel(float* __restrict__ out, int N) {
    __shared__ float s_red[8];
    int tid = threadIdx.x;
    float s = 0.0f;
    for (int i = tid; i < N; i += 256) s += g_loss[i];
    int lane = tid & 31, w = tid >> 5;
    #pragma unroll
    for (int o = 16; o; o >>= 1) s += __shfl_xor_sync(0xffffffffu, s, o);
    if (lane == 0) s_red[w] = s;
    __syncthreads();
    if (tid == 0) {
        float tot = 0.0f;
        #pragma unroll
        for (int ww = 0; ww < 8; ++ww) tot += s_red[ww];
        out[0] = tot / (float)N;
    }
}

// ---------------- launch --------------------------------------------------------
extern "C" void kernel_launch(void* const* d_in, const int* in_sizes, int n_in,
                              void* d_out, int out_size) {
    const float* emb   = (const float*)d_in[0];
    const int*   pp    = (const int*)d_in[1];
    const int*   stage = (const int*)d_in[2];

    int N      = in_sizes[0] / D;        // 4096
    int npairs = in_sizes[1] / 2;        // 4096

    build_q_kernel<<<(npairs + 255) / 256, 256>>>(pp, npairs);
    prep_kernel<<<N, D>>>(emb, N);

    int nb   = N >> 7;
    int nblk = nb * (nb + 1) / 2;        // upper triangle
    int smem = 128 * LDS * 4;            // 67584 bytes (bf16 tiles fit inside)
    cudaFuncSetAttribute(gemm_wmma_kernel,
                         cudaFuncAttributeMaxDynamicSharedMemorySize, smem);
    gemm_wmma_kernel<<<nblk, 256, smem>>>(N);

    int rank = (int)(0.8 * (double)(N - 1) + 1e-9);   // 3276 for N=4096
    select_kernel<<<N, 256>>>(stage, N, rank);

    reduce_kernel<<<1, 256>>>((float*)d_out, N);
}

// round 12
// speedup vs baseline: 2.5504x; 1.0718x over previous
#include <cuda_runtime.h>
#include <cuda_bf16.h>
#include <cuda_fp16.h>
#include <mma.h>
#include <math.h>
#include <stdint.h>

using namespace nvcuda;

#define MAXN 4096
#define D    128

// ---------------- scratch (device globals; no allocation allowed) -------------
__device__ __half        g_S[(size_t)MAXN * MAXN]; // exp(sim/tau) in fp16, masked = 0
__device__ __nv_bfloat16 g_hn[MAXN * D];           // normalized hard_neg rows (bf16)
__device__ float         g_pos[MAXN];              // exp(cos(hp_x, hp_qx)/tau)
__device__ float         g_loss[MAXN];
__device__ int           g_q[MAXN];                // positive-pair partner

// ---------------- K0: build partner map ---------------------------------------
__global__ void build_q_kernel(const int* __restrict__ pp, int npairs) {
    int r = blockIdx.x * blockDim.x + threadIdx.x;
    if (r < npairs) g_q[pp[2 * r]] = pp[2 * r + 1];
}

// ---------------- K1: normalized hard_neg rows (bf16) + pos --------------------
__global__ void prep_kernel(const float* __restrict__ emb, int N) {
    int x = blockIdx.x;
    int d = threadIdx.x;
    int qx = g_q[x];
    int fx = N - 1;
    while (fx == x || fx == qx) fx--;   // largest index not in {x, q[x]}

    float a  = emb[(size_t)x  * D + d];
    float b  = emb[(size_t)qx * D + d];
    float pf = emb[(size_t)fx * D + d];
    float h  = 0.5f * (a + pf);

    float v0 = h * h, v1 = a * a, v2 = b * b, v3 = a * b;
    __shared__ float sh[4][4];
    int lane = d & 31, w = d >> 5;
    #pragma unroll
    for (int o = 16; o; o >>= 1) {
        v0 += __shfl_xor_sync(0xffffffffu, v0, o);
        v1 += __shfl_xor_sync(0xffffffffu, v1, o);
        v2 += __shfl_xor_sync(0xffffffffu, v2, o);
        v3 += __shfl_xor_sync(0xffffffffu, v3, o);
    }
    if (lane == 0) { sh[0][w] = v0; sh[1][w] = v1; sh[2][w] = v2; sh[3][w] = v3; }
    __syncthreads();
    float nn = sh[0][0] + sh[0][1] + sh[0][2] + sh[0][3];
    float inv = 1.0f / fmaxf(sqrtf(nn), 1e-8f);
    g_hn[(size_t)x * D + d] = __float2bfloat16(h * inv);

    if (d == 0) {
        float aa = sh[1][0] + sh[1][1] + sh[1][2] + sh[1][3];
        float bb = sh[2][0] + sh[2][1] + sh[2][2] + sh[2][3];
        float ab = sh[3][0] + sh[3][1] + sh[3][2] + sh[3][3];
        float dot = 2.5f * ab - 0.75f * (aa + bb);
        float nxx = 2.25f * aa + 0.25f * bb - 1.5f * ab;
        float nyy = 2.25f * bb + 0.25f * aa - 1.5f * ab;
        float nx = fmaxf(sqrtf(nxx), 1e-8f);
        float ny = fmaxf(sqrtf(nyy), 1e-8f);
        g_pos[x] = expf((dot / (nx * ny)) * 5.0f);
    }
}

// ---------------- K2: WMMA bf16 GEMM + exp + mask (fp16 out, TRIANGLE) ---------
// 128x128 tile per CTA, upper triangle only (528 CTAs), mirror store.
// 2 CTAs/SM (forced) for cross-CTA latency hiding. Mask+exp fused into BOTH
// store loops (no separate pass; exp is MUFU-cheap).
#define KP  72
#define TSZ (128 * KP)       // bf16 elements per tile
#define LDS 132              // staging row stride (floats); 528B = 33*16B -> legal

__global__ void __launch_bounds__(256, 2) gemm_wmma_kernel(int N) {
    extern __shared__ char smem[];
    __nv_bfloat16* Ah = (__nv_bfloat16*)smem;
    __nv_bfloat16* Bh = Ah + TSZ;
    float* Tst = (float*)smem;          // epilogue staging 128 x LDS (reuses tiles)
    __shared__ int s_qa[128];           // q[m0 + r]
    __shared__ int s_qb[128];           // q[n0 + c]

    int nb = N >> 7;
    int bid = blockIdx.x;
    int bi = 0, rem = bid;
    while (rem >= nb - bi) { rem -= nb - bi; bi++; }
    int bj = bi + rem;                  // bj >= bi
    int m0 = bi * 128, n0 = bj * 128;

    int tid = threadIdx.x, wid = tid >> 5;
    int wm = wid >> 1, wn = wid & 1;    // warp tile: rows wm*32..+32, cols wn*64..+64

    if (tid < 128)      s_qa[tid]       = g_q[m0 + tid];
    else                s_qb[tid - 128] = g_q[n0 + (tid - 128)];

    wmma::fragment<wmma::accumulator, 16, 16, 16, float> acc[2][4];
    #pragma unroll
    for (int i = 0; i < 2; ++i)
        #pragma unroll
        for (int j = 0; j < 4; ++j) wmma::fill_fragment(acc[i][j], 0.0f);

    #pragma unroll
    for (int ch = 0; ch < 2; ++ch) {
        const __nv_bfloat16* srcA = g_hn + (size_t)bi * 128 * D + ch * 64;
        const __nv_bfloat16* srcB = g_hn + (size_t)bj * 128 * D + ch * 64;
        #pragma unroll
        for (int i = tid; i < 1024; i += 256) {   // 1024 uint4 per tile
            int row = i >> 3, c8 = i & 7;
            *(uint4*)(Ah + row * KP + c8 * 8) = *(const uint4*)(srcA + (size_t)row * D + c8 * 8);
            *(uint4*)(Bh + row * KP + c8 * 8) = *(const uint4*)(srcB + (size_t)row * D + c8 * 8);
        }
        __syncthreads();

        #pragma unroll
        for (int ks = 0; ks < 4; ++ks) {
            wmma::fragment<wmma::matrix_a, 16, 16, 16, __nv_bfloat16, wmma::row_major> a_f[2];
            wmma::fragment<wmma::matrix_b, 16, 16, 16, __nv_bfloat16, wmma::col_major> b_f[4];
            #pragma unroll
            for (int i = 0; i < 2; ++i)
                wmma::load_matrix_sync(a_f[i], Ah + (wm * 32 + i * 16) * KP + ks * 16, KP);
            #pragma unroll
            for (int j = 0; j < 4; ++j)
                wmma::load_matrix_sync(b_f[j], Bh + (wn * 64 + j * 16) * KP + ks * 16, KP);
            #pragma unroll
            for (int i = 0; i < 2; ++i)
                #pragma unroll
                for (int j = 0; j < 4; ++j)
                    wmma::mma_sync(acc[i][j], a_f[i], b_f[j], acc[i][j]);
        }
        __syncthreads();
    }

    // stage raw accumulators to smem (ldm = 132 floats = 528B, multiple of 16B)
    #pragma unroll
    for (int i = 0; i < 2; ++i)
        #pragma unroll
        for (int j = 0; j < 4; ++j)
            wmma::store_matrix_sync(Tst + (wm * 32 + i * 16) * LDS + wn * 64 + j * 16,
                                    acc[i][j], LDS, wmma::mem_row_major);
    __syncthreads();

    // direct store: thread -> 8 consecutive cols of one row; fused mask+exp; STG.128
    {
        int rbase = tid >> 4;            // 0..15
        int c8 = (tid & 15) * 8;         // 0,8,..,120
        #pragma unroll
        for (int p = 0; p < 8; ++p) {
            int r = p * 16 + rbase;
            int m = m0 + r, qm = s_qa[r];
            const float* src = Tst + r * LDS + c8;
            unsigned pkw[4];
            #pragma unroll
            for (int h2 = 0; h2 < 4; ++h2) {
                int n_a = n0 + c8 + 2 * h2, n_b = n_a + 1;
                float fa = (n_a == m || n_a == qm) ? 0.0f : __expf(src[2 * h2]     * 5.0f);
                float fb = (n_b == m || n_b == qm) ? 0.0f : __expf(src[2 * h2 + 1] * 5.0f);
                __half2 hh = __floats2half2_rn(fa, fb);
                pkw[h2] = *(unsigned*)&hh;
            }
            *(uint4*)(g_S + (size_t)m * N + n0 + c8) =
                make_uint4(pkw[0], pkw[1], pkw[2], pkw[3]);
        }
    }
    // mirror store: thread owns staging column c; gathers 8 rows; fused mask+exp
    // (lane-consecutive word reads: conflict-free)
    {
        int c    = tid & 127;
        int hseg = tid >> 7;             // 0/1 -> r halves
        int nrow = n0 + c, qn = s_qb[c];
        #pragma unroll
        for (int j = 0; j < 8; ++j) {
            int r0 = hseg * 64 + j * 8;
            unsigned pkw[4];
            #pragma unroll
            for (int h2 = 0; h2 < 4; ++h2) {
                int m_a = m0 + r0 + 2 * h2, m_b = m_a + 1;
                float fa = (m_a == nrow || m_a == qn) ? 0.0f
                         : __expf(Tst[(r0 + 2 * h2)     * LDS + c] * 5.0f);
                float fb = (m_b == nrow || m_b == qn) ? 0.0f
                         : __expf(Tst[(r0 + 2 * h2 + 1) * LDS + c] * 5.0f);
                __half2 hh = __floats2half2_rn(fa, fb);
                pkw[h2] = *(unsigned*)&hh;
            }
            *(uint4*)(g_S + (size_t)nrow * N + m0 + r0) =
                make_uint4(pkw[0], pkw[1], pkw[2], pkw[3]);
        }
    }
}

// ---------------- K3 helper: scan 8 privatized histogram copies -----------------
// (fold happens inside the scan: no separate fold pass / syncs)
__device__ __forceinline__ void locate_bin256x8(unsigned* hist, unsigned k,
                                                unsigned* s_warp, int* s_bin, int* s_krem) {
    int tid = threadIdx.x;
    unsigned local = 0;
    #pragma unroll
    for (int i = 0; i < 8; ++i) local += hist[tid + 256 * i];
    unsigned inc = local;
    int lane = tid & 31, w = tid >> 5;
    #pragma unroll
    for (int o = 1; o < 32; o <<= 1) {
        unsigned t = __shfl_up_sync(0xffffffffu, inc, o);
        if (lane >= o) inc += t;
    }
    if (lane == 31) s_warp[w] = inc;
    __syncthreads();
    unsigned woff = 0;
    for (int ww = 0; ww < w; ++ww) woff += s_warp[ww];
    unsigned excl = woff + inc - local;
    if (excl <= k && k < excl + local) { *s_bin = tid; *s_krem = (int)(k - excl); }
    __syncthreads();
}

// ---------------- K3: per-row exact radix select + thresholded sum (fp16) ------
// one CTA (256 threads) per row; 16 fp16 values/thread kept PACKED (8 u32 regs);
// 2-level radix on fp16 bits [15:8],[7:0], 8-way warp-privatized histograms.
__global__ void __launch_bounds__(256) select_kernel(const int* __restrict__ stage_ptr,
                                                     int N, int rank) {
    __shared__ unsigned hist[2048];     // 8 warp-private copies of 256 bins
    __shared__ unsigned s_warp[8];
    __shared__ int      s_bin, s_krem;
    __shared__ float    s_red[8];

    int x = blockIdx.x, tid = threadIdx.x, wid = tid >> 5;
    const uint4* row16 = (const uint4*)(g_S + (size_t)x * N);   // 8 fp16 per uint4
    uint4 p0 = row16[tid];
    uint4 p1 = row16[tid + 256];
    unsigned pk[8] = {p0.x, p0.y, p0.z, p0.w, p1.x, p1.y, p1.z, p1.w};

    int stage = *stage_ptr;
    float ssum = 0.0f;
    unsigned hbase = (unsigned)wid << 8;

    if (stage) {
        // ---- L0: fp16 bits [15:8] ----
        #pragma unroll
        for (int i = 0; i < 8; ++i) hist[tid + 256 * i] = 0;
        __syncthreads();
        #pragma unroll
        for (int r = 0; r < 8; ++r) {
            atomicAdd(&hist[hbase + ((pk[r] >> 8)  & 0xffu)], 1u);
            atomicAdd(&hist[hbase + ((pk[r] >> 24) & 0xffu)], 1u);
        }
        __syncthreads();
        locate_bin256x8(hist, (unsigned)rank, s_warp, &s_bin, &s_krem);
        unsigned b0 = (unsigned)s_bin;
        unsigned k1 = (unsigned)s_krem;
        __syncthreads();

        // ---- L1: fp16 bits [7:0] within bin b0 ----
        #pragma unroll
        for (int i = 0; i < 8; ++i) hist[tid + 256 * i] = 0;
        __syncthreads();
        #pragma unroll
        for (int r = 0; r < 8; ++r) {
            unsigned lo = pk[r] & 0xffffu, hi = pk[r] >> 16;
            if ((lo >> 8) == b0) atomicAdd(&hist[hbase + (lo & 0xffu)], 1u);
            if ((hi >> 8) == b0) atomicAdd(&hist[hbase + (hi & 0xffu)], 1u);
        }
        __syncthreads();
        locate_bin256x8(hist, k1, s_warp, &s_bin, &s_krem);
        unsigned tbits = (b0 << 8) | (unsigned)s_bin;   // exact rank-th fp16 value

        #pragma unroll
        for (int r = 0; r < 8; ++r) {
            unsigned lo = pk[r] & 0xffffu, hi = pk[r] >> 16;
            if (lo >= tbits) ssum += __half2float(__ushort_as_half((unsigned short)lo));
            if (hi >= tbits) ssum += __half2float(__ushort_as_half((unsigned short)hi));
        }
    } else {
        #pragma unroll
        for (int r = 0; r < 8; ++r) {
            ssum += __half2float(__ushort_as_half((unsigned short)(pk[r] & 0xffffu)));
            ssum += __half2float(__ushort_as_half((unsigned short)(pk[r] >> 16)));
        }
    }

    int lane = tid & 31, w = tid >> 5;
    #pragma unroll
    for (int o = 16; o; o >>= 1) ssum += __shfl_xor_sync(0xffffffffu, ssum, o);
    if (lane == 0) s_red[w] = ssum;
    __syncthreads();
    if (tid == 0) {
        float tot = 0.0f;
        #pragma unroll
        for (int ww = 0; ww < 8; ++ww) tot += s_red[ww];
        float pos = g_pos[x];
        g_loss[x] = -logf(pos / (pos + tot));
    }
}

// ---------------- K4: deterministic mean reduce --------------------------------
__global__ void reduce_kernel(float* __restrict__ out, int N) {
    __shared__ float s_red[8];
    int tid = threadIdx.x;
    float s = 0.0f;
    for (int i = tid; i < N; i += 256) s += g_loss[i];
    int lane = tid & 31, w = tid >> 5;
    #pragma unroll
    for (int o = 16; o; o >>= 1) s += __shfl_xor_sync(0xffffffffu, s, o);
    if (lane == 0) s_red[w] = s;
    __syncthreads();
    if (tid == 0) {
        float tot = 0.0f;
        #pragma unroll
        for (int ww = 0; ww < 8; ++ww) tot += s_red[ww];
        out[0] = tot / (float)N;
    }
}

// ---------------- launch --------------------------------------------------------
extern "C" void kernel_launch(void* const* d_in, const int* in_sizes, int n_in,
                              void* d_out, int out_size) {
    const float* emb   = (const float*)d_in[0];
    const int*   pp    = (const int*)d_in[1];
    const int*   stage = (const int*)d_in[2];

    int N      = in_sizes[0] / D;        // 4096
    int npairs = in_sizes[1] / 2;        // 4096

    build_q_kernel<<<(npairs + 255) / 256, 256>>>(pp, npairs);
    prep_kernel<<<N, D>>>(emb, N);

    int nb   = N >> 7;
    int nblk = nb * (nb + 1) / 2;        // upper triangle
    int smem = 128 * LDS * 4;            // 67584 bytes (bf16 tiles fit inside)
    cudaFuncSetAttribute(gemm_wmma_kernel,
                         cudaFuncAttributeMaxDynamicSharedMemorySize, smem);
    gemm_wmma_kernel<<<nblk, 256, smem>>>(N);

    int rank = (int)(0.8 * (double)(N - 1) + 1e-9);   // 3276 for N=4096
    select_kernel<<<N, 256>>>(stage, N, rank);

    reduce_kernel<<<1, 256>>>((float*)d_out, N);
}